// round 7
// baseline (speedup 1.0000x reference)
#include <cuda_runtime.h>

// Shapes fixed by the problem
#define BB 16
#define XL 1024
#define YL 1024
#define DD 1024
#define NEG_INF (-1e20f)

// ---------------------------------------------------------------------------
// SMEM: two 64KB stages, each {A_HI,A_LO,B_HI,B_LO} 16KB tiles
// (128 rows x 128B, SW128-swizzled, K-major) + mask.
// ---------------------------------------------------------------------------
#define OFF_A_HI 0
#define OFF_A_LO 16384
#define OFF_B_HI 32768
#define OFF_B_LO 49152
#define STAGE_STRIDE 65536
#define OFF_MASK 131072
#define SMEM_BYTES (131072 + 512)

// ---------------------------------------------------------------------------
// Helpers
// ---------------------------------------------------------------------------
static __device__ __forceinline__ unsigned smem_u32(const void* p) {
    unsigned a;
    asm("{ .reg .u64 t; cvta.to.shared.u64 t, %1; cvt.u32.u64 %0, t; }"
        : "=r"(a) : "l"(p));
    return a;
}
static __device__ __forceinline__ float tf32_rna(float x) {
    unsigned u;
    asm("cvt.rna.tf32.f32 %0, %1;" : "=r"(u) : "f"(x));
    return __uint_as_float(u);
}
static __device__ __forceinline__ void split4(float4 v, float4& h, float4& l) {
    h.x = tf32_rna(v.x); l.x = tf32_rna(v.x - h.x);
    h.y = tf32_rna(v.y); l.y = tf32_rna(v.y - h.y);
    h.z = tf32_rna(v.z); l.z = tf32_rna(v.z - h.z);
    h.w = tf32_rna(v.w); l.w = tf32_rna(v.w - h.w);
}

#define LDSM_X4(r, addr)                                                      \
    asm volatile(                                                             \
        "ldmatrix.sync.aligned.m8n8.x4.shared.b16 {%0,%1,%2,%3}, [%4];"       \
        : "=r"((r)[0]), "=r"((r)[1]), "=r"((r)[2]), "=r"((r)[3])              \
        : "r"(addr))

#define MMA_TF32(d, a, b0, b1)                                                \
    asm volatile(                                                             \
        "mma.sync.aligned.m16n8k8.row.col.f32.tf32.tf32.f32 "                 \
        "{%0,%1,%2,%3}, {%4,%5,%6,%7}, {%8,%9}, {%0,%1,%2,%3};"               \
        : "+f"((d)[0]), "+f"((d)[1]), "+f"((d)[2]), "+f"((d)[3])              \
        : "r"((a)[0]), "r"((a)[1]), "r"((a)[2]), "r"((a)[3]),                 \
          "r"(b0), "r"(b1))

// ---------------------------------------------------------------------------
// MMA over one resident K-chunk. 8 warps, warp tile 64x32:
// 4 m16 x 4 n8 tiles, 3xTF32 products (hh, lh, hl).
// ---------------------------------------------------------------------------
static __device__ __forceinline__ void mma_chunk(
    unsigned base, unsigned aRow, unsigned bRow, unsigned cA, unsigned cB,
    unsigned xr, float acc[4][4][4])
{
    unsigned fa[4][4], fb[2][4], fc[4][4];
#pragma unroll
    for (int k8 = 0; k8 < 4; ++k8) {
        const unsigned colA = ((unsigned)(k8 * 32) + cA) ^ xr;
        const unsigned colB = ((unsigned)(k8 * 32) + cB) ^ xr;
#pragma unroll
        for (int i = 0; i < 4; ++i)
            LDSM_X4(fa[i], base + OFF_A_HI + aRow + 2048u * i + colA);
#pragma unroll
        for (int jp = 0; jp < 2; ++jp)
            LDSM_X4(fb[jp], base + OFF_B_HI + bRow + 2048u * jp + colB);
#pragma unroll
        for (int i = 0; i < 4; ++i)
            LDSM_X4(fc[i], base + OFF_A_LO + aRow + 2048u * i + colA);

        // hi*hi
#pragma unroll
        for (int i = 0; i < 4; ++i)
#pragma unroll
            for (int j = 0; j < 4; ++j)
                MMA_TF32(acc[i][j], fa[i], fb[j >> 1][(j & 1) * 2],
                         fb[j >> 1][(j & 1) * 2 + 1]);
        // lo*hi
#pragma unroll
        for (int i = 0; i < 4; ++i)
#pragma unroll
            for (int j = 0; j < 4; ++j)
                MMA_TF32(acc[i][j], fc[i], fb[j >> 1][(j & 1) * 2],
                         fb[j >> 1][(j & 1) * 2 + 1]);
        // hi*lo
#pragma unroll
        for (int jp = 0; jp < 2; ++jp)
            LDSM_X4(fc[jp], base + OFF_B_LO + bRow + 2048u * jp + colB);
#pragma unroll
        for (int i = 0; i < 4; ++i)
#pragma unroll
            for (int j = 0; j < 4; ++j)
                MMA_TF32(acc[i][j], fa[i], fc[j >> 1][(j & 1) * 2],
                         fc[j >> 1][(j & 1) * 2 + 1]);
    }
}

// ---------------------------------------------------------------------------
// Kernel 1: scores = xs @ ys^T, mask fused. Double-buffered pipeline.
// ---------------------------------------------------------------------------
__global__ __launch_bounds__(256, 1)
void scores_tc_kernel(const float* __restrict__ xs,
                      const float* __restrict__ ys,
                      const int* __restrict__ mask,
                      float* __restrict__ w)
{
    extern __shared__ char smem[];
    const unsigned sb = smem_u32(smem);
    const int t = threadIdx.x;
    const int wid = t >> 5;
    const int lane = t & 31;
    const int b = blockIdx.z;
    const int rowBase = blockIdx.y * 128;
    const int colBase = blockIdx.x * 128;

    const int m0 = (wid & 1) * 64;
    const int n0 = (wid >> 1) * 32;

    // fragment address geometry (unchanged from R6-passing kernel)
    const unsigned xr = (unsigned)(lane & 7) << 4;
    const unsigned rA = (unsigned)((lane & 7) + ((lane >> 3) & 1) * 8);
    const unsigned cA = (unsigned)((lane >> 4) << 4);
    const unsigned rB = (unsigned)((lane & 7) + ((lane >> 4) & 1) * 8);
    const unsigned cB = (unsigned)(((lane >> 3) & 1) << 4);
    const unsigned aRow = ((unsigned)m0 + rA) * 128u;
    const unsigned bRow = ((unsigned)n0 + rB) * 128u;

    if (t < 128)
        ((int*)(smem + OFF_MASK))[t] = mask[b * YL + colBase + t];

    float acc[4][4][4];
#pragma unroll
    for (int i = 0; i < 4; ++i)
#pragma unroll
        for (int j = 0; j < 4; ++j)
#pragma unroll
            for (int d = 0; d < 4; ++d) acc[i][j][d] = 0.0f;

    const float* A  = xs + (size_t)b * XL * DD + (size_t)rowBase * DD;
    const float* Bp = ys + (size_t)b * YL * DD + (size_t)colBase * DD;

    // per-thread load slots: 4 float4 of A + 4 of B (256 threads)
    int lr[4], lc4[4];
    unsigned loff[4];
#pragma unroll
    for (int i = 0; i < 4; ++i) {
        int s = t + i * 256;
        lr[i]  = s >> 3;
        lc4[i] = s & 7;
        loff[i] = (unsigned)lr[i] * 128u +
                  (((unsigned)lc4[i] * 16u) ^ (((unsigned)(lr[i] & 7)) << 4));
    }

    // prologue: chunk 0 -> stage 0
#pragma unroll
    for (int i = 0; i < 4; ++i) {
        float4 va = *reinterpret_cast<const float4*>(A  + (size_t)lr[i] * DD + lc4[i] * 4);
        float4 vb = *reinterpret_cast<const float4*>(Bp + (size_t)lr[i] * DD + lc4[i] * 4);
        float4 h, l;
        split4(va, h, l);
        *reinterpret_cast<float4*>(smem + OFF_A_HI + loff[i]) = h;
        *reinterpret_cast<float4*>(smem + OFF_A_LO + loff[i]) = l;
        split4(vb, h, l);
        *reinterpret_cast<float4*>(smem + OFF_B_HI + loff[i]) = h;
        *reinterpret_cast<float4*>(smem + OFF_B_LO + loff[i]) = l;
    }
    __syncthreads();

    for (int it = 0; it < 32; ++it) {
        float4 pa[4], pb[4];
        if (it < 31) {
            const int k0 = (it + 1) * 32;
#pragma unroll
            for (int i = 0; i < 4; ++i) {
                pa[i] = *reinterpret_cast<const float4*>(A  + (size_t)lr[i] * DD + k0 + lc4[i] * 4);
                pb[i] = *reinterpret_cast<const float4*>(Bp + (size_t)lr[i] * DD + k0 + lc4[i] * 4);
            }
        }

        mma_chunk(sb + (unsigned)(it & 1) * STAGE_STRIDE,
                  aRow, bRow, cA, cB, xr, acc);

        if (it < 31) {
            char* st = smem + ((it + 1) & 1) * STAGE_STRIDE;
#pragma unroll
            for (int i = 0; i < 4; ++i) {
                float4 h, l;
                split4(pa[i], h, l);
                *reinterpret_cast<float4*>(st + OFF_A_HI + loff[i]) = h;
                *reinterpret_cast<float4*>(st + OFF_A_LO + loff[i]) = l;
                split4(pb[i], h, l);
                *reinterpret_cast<float4*>(st + OFF_B_HI + loff[i]) = h;
                *reinterpret_cast<float4*>(st + OFF_B_LO + loff[i]) = l;
            }
        }
        __syncthreads();
    }

    // masked epilogue
    const int* ms = (const int*)(smem + OFF_MASK);
    float* wbase = w + (size_t)b * XL * YL + colBase;
    const int g = lane >> 2;
    const int cp = (lane & 3) * 2;
#pragma unroll
    for (int i = 0; i < 4; ++i) {
        const int row = rowBase + m0 + 16 * i + g;
#pragma unroll
        for (int j = 0; j < 4; ++j) {
            const int col = n0 + 8 * j + cp;
            const int mk0 = ms[col];
            const int mk1 = ms[col + 1];
            float2 v;
            v.x = mk0 ? acc[i][j][0] : NEG_INF;
            v.y = mk1 ? acc[i][j][1] : NEG_INF;
            *reinterpret_cast<float2*>(wbase + (size_t)row * YL + col) = v;
            v.x = mk0 ? acc[i][j][2] : NEG_INF;
            v.y = mk1 ? acc[i][j][3] : NEG_INF;
            *reinterpret_cast<float2*>(wbase + (size_t)(row + 8) * YL + col) = v;
        }
    }
}

// ---------------------------------------------------------------------------
// Kernel 2: in-place row softmax over YL=1024
// ---------------------------------------------------------------------------
__global__ __launch_bounds__(256)
void softmax_kernel(float* __restrict__ w)
{
    __shared__ float red[256];
    const int row = blockIdx.x;
    float* p = w + (size_t)row * YL;
    const int t = threadIdx.x;

    float4 v = reinterpret_cast<float4*>(p)[t];

    float m = fmaxf(fmaxf(v.x, v.y), fmaxf(v.z, v.w));
    red[t] = m;
    __syncthreads();
    for (int s = 128; s > 0; s >>= 1) {
        if (t < s) red[t] = fmaxf(red[t], red[t + s]);
        __syncthreads();
    }
    m = red[0];
    __syncthreads();

    float e0 = expf(v.x - m);
    float e1 = expf(v.y - m);
    float e2 = expf(v.z - m);
    float e3 = expf(v.w - m);

    red[t] = e0 + e1 + e2 + e3;
    __syncthreads();
    for (int s = 128; s > 0; s >>= 1) {
        if (t < s) red[t] += red[t + s];
        __syncthreads();
    }
    float inv = 1.0f / red[0];

    float4 o;
    o.x = e0 * inv; o.y = e1 * inv; o.z = e2 * inv; o.w = e3 * inv;
    reinterpret_cast<float4*>(p)[t] = o;
}

// ---------------------------------------------------------------------------
// Kernel 3: emb = weight @ ys. Double-buffered; ys transposed into K-major smem.
// ---------------------------------------------------------------------------
__global__ __launch_bounds__(256, 1)
void emb_tc_kernel(const float* __restrict__ w,
                   const float* __restrict__ ys,
                   float* __restrict__ emb)
{
    extern __shared__ char smem[];
    const unsigned sb = smem_u32(smem);
    const int t = threadIdx.x;
    const int wid = t >> 5;
    const int lane = t & 31;
    const int b = blockIdx.z;
    const int rowBase = blockIdx.y * 128;   // x
    const int colBase = blockIdx.x * 128;   // d

    const int m0 = (wid & 1) * 64;
    const int n0 = (wid >> 1) * 32;

    const unsigned xr = (unsigned)(lane & 7) << 4;
    const unsigned rA = (unsigned)((lane & 7) + ((lane >> 3) & 1) * 8);
    const unsigned cA = (unsigned)((lane >> 4) << 4);
    const unsigned rB = (unsigned)((lane & 7) + ((lane >> 4) & 1) * 8);
    const unsigned cB = (unsigned)(((lane >> 3) & 1) << 4);
    const unsigned aRow = ((unsigned)m0 + rA) * 128u;
    const unsigned bRow = ((unsigned)n0 + rB) * 128u;

    float acc[4][4][4];
#pragma unroll
    for (int i = 0; i < 4; ++i)
#pragma unroll
        for (int j = 0; j < 4; ++j)
#pragma unroll
            for (int d = 0; d < 4; ++d) acc[i][j][d] = 0.0f;

    const float* A   = w  + (size_t)b * XL * YL + (size_t)rowBase * YL;
    const float* Byb = ys + (size_t)b * YL * DD + colBase;

    // A slots (4 float4/thread)
    int lr[4], lc4[4];
    unsigned loff[4];
#pragma unroll
    for (int i = 0; i < 4; ++i) {
        int s = t + i * 256;
        lr[i]  = s >> 3;
        lc4[i] = s & 7;
        loff[i] = (unsigned)lr[i] * 128u +
                  (((unsigned)lc4[i] * 16u) ^ (((unsigned)(lr[i] & 7)) << 4));
    }
    // B slots: thread owns d-column dcol, k-half kh (16 k each -> 4 gathered float4)
    const int dcol = t & 127;
    const int kh   = (t >> 7) * 16;
    unsigned boff[4];
#pragma unroll
    for (int q = 0; q < 4; ++q)
        boff[q] = (unsigned)dcol * 128u +
                  (((unsigned)(kh * 4 + q * 16)) ^ (((unsigned)(dcol & 7)) << 4));

    // prologue: chunk 0 -> stage 0
    {
#pragma unroll
        for (int i = 0; i < 4; ++i) {
            float4 va = *reinterpret_cast<const float4*>(A + (size_t)lr[i] * YL + lc4[i] * 4);
            float4 h, l;
            split4(va, h, l);
            *reinterpret_cast<float4*>(smem + OFF_A_HI + loff[i]) = h;
            *reinterpret_cast<float4*>(smem + OFF_A_LO + loff[i]) = l;
        }
        const float* bp = Byb + (size_t)kh * DD + dcol;
#pragma unroll
        for (int q = 0; q < 4; ++q) {
            float4 vv;
            vv.x = bp[(size_t)(q * 4 + 0) * DD];
            vv.y = bp[(size_t)(q * 4 + 1) * DD];
            vv.z = bp[(size_t)(q * 4 + 2) * DD];
            vv.w = bp[(size_t)(q * 4 + 3) * DD];
            float4 h, l;
            split4(vv, h, l);
            *reinterpret_cast<float4*>(smem + OFF_B_HI + boff[q]) = h;
            *reinterpret_cast<float4*>(smem + OFF_B_LO + boff[q]) = l;
        }
    }
    __syncthreads();

    for (int it = 0; it < 32; ++it) {
        float4 pa[4], pb[4];
        if (it < 31) {
            const int k0 = (it + 1) * 32;
#pragma unroll
            for (int i = 0; i < 4; ++i)
                pa[i] = *reinterpret_cast<const float4*>(A + (size_t)lr[i] * YL + k0 + lc4[i] * 4);
            const float* bp = Byb + (size_t)(k0 + kh) * DD + dcol;
#pragma unroll
            for (int q = 0; q < 4; ++q) {
                pb[q].x = bp[(size_t)(q * 4 + 0) * DD];
                pb[q].y = bp[(size_t)(q * 4 + 1) * DD];
                pb[q].z = bp[(size_t)(q * 4 + 2) * DD];
                pb[q].w = bp[(size_t)(q * 4 + 3) * DD];
            }
        }

        mma_chunk(sb + (unsigned)(it & 1) * STAGE_STRIDE,
                  aRow, bRow, cA, cB, xr, acc);

        if (it < 31) {
            char* st = smem + ((it + 1) & 1) * STAGE_STRIDE;
#pragma unroll
            for (int i = 0; i < 4; ++i) {
                float4 h, l;
                split4(pa[i], h, l);
                *reinterpret_cast<float4*>(st + OFF_A_HI + loff[i]) = h;
                *reinterpret_cast<float4*>(st + OFF_A_LO + loff[i]) = l;
            }
#pragma unroll
            for (int q = 0; q < 4; ++q) {
                float4 h, l;
                split4(pb[q], h, l);
                *reinterpret_cast<float4*>(st + OFF_B_HI + boff[q]) = h;
                *reinterpret_cast<float4*>(st + OFF_B_LO + boff[q]) = l;
            }
        }
        __syncthreads();
    }

    float* obase = emb + (size_t)b * XL * DD + colBase;
    const int g = lane >> 2;
    const int cp = (lane & 3) * 2;
#pragma unroll
    for (int i = 0; i < 4; ++i) {
        const int row = rowBase + m0 + 16 * i + g;
#pragma unroll
        for (int j = 0; j < 4; ++j) {
            const int col = n0 + 8 * j + cp;
            float2 v;
            v.x = acc[i][j][0];
            v.y = acc[i][j][1];
            *reinterpret_cast<float2*>(obase + (size_t)row * DD + col) = v;
            v.x = acc[i][j][2];
            v.y = acc[i][j][3];
            *reinterpret_cast<float2*>(obase + (size_t)(row + 8) * DD + col) = v;
        }
    }
}

// ---------------------------------------------------------------------------
extern "C" void kernel_launch(void* const* d_in, const int* in_sizes, int n_in,
                              void* d_out, int out_size)
{
    const float* xs   = (const float*)d_in[0];
    const float* ys   = (const float*)d_in[1];
    const int*   mask = (const int*)d_in[2];

    float* emb = (float*)d_out;                           // [B, XL, D]
    float* w   = (float*)d_out + (size_t)BB * XL * DD;    // [B, XL, YL]

    cudaFuncSetAttribute(scores_tc_kernel,
                         cudaFuncAttributeMaxDynamicSharedMemorySize, SMEM_BYTES);
    cudaFuncSetAttribute(emb_tc_kernel,
                         cudaFuncAttributeMaxDynamicSharedMemorySize, SMEM_BYTES);

    dim3 block(256);
    scores_tc_kernel<<<dim3(8, 8, BB), block, SMEM_BYTES>>>(xs, ys, mask, w);
    softmax_kernel<<<BB * XL, 256>>>(w);
    emb_tc_kernel<<<dim3(8, 8, BB), block, SMEM_BYTES>>>(w, ys, emb);
}